// round 1
// baseline (speedup 1.0000x reference)
#include <cuda_runtime.h>

// HDB-LUT 2x super-resolution, fused single pass.
// out[b, 2y+p, 2x+q] = (1/3) * sum over ktype in {h,d,b}, r in {0..3} of
//   weight_ktype[a*L^2 + b_s*L + c_s][perm_r(p,q)]
// where a,b_s,c_s are clamped neighborhood samples in the r-rotated frame,
// mapped back to original coordinates analytically.

#define NN 512
#define BDIM 256

__global__ __launch_bounds__(BDIM) void hdblut_kernel(
    const int* __restrict__ img,
    const float4* __restrict__ wh,
    const float4* __restrict__ wd,
    const float4* __restrict__ wb,
    float* __restrict__ out)
{
    const int x  = blockIdx.x * BDIM + threadIdx.x;
    const int y  = blockIdx.y;
    const int bz = blockIdx.z;

    const int* im = img + (size_t)bz * NN * NN;

    const int xm2 = max(x - 2, 0),  xm1 = max(x - 1, 0);
    const int xp1 = min(x + 1, NN - 1), xp2 = min(x + 2, NN - 1);
    const int ym2 = max(y - 2, 0),  ym1 = max(y - 1, 0);
    const int yp1 = min(y + 1, NN - 1), yp2 = min(y + 2, NN - 1);

    const int* r_m2 = im + (size_t)ym2 * NN;
    const int* r_m1 = im + (size_t)ym1 * NN;
    const int* r_0  = im + (size_t)y   * NN;
    const int* r_p1 = im + (size_t)yp1 * NN;
    const int* r_p2 = im + (size_t)yp2 * NN;

    const int a = r_0[x];

    // (b,c) sample pairs for 12 combos: k = ktype*4 + r
    // ktype 0 = 'h' (offsets (0,1),(0,2)), 1 = 'd' ((1,1),(2,2)), 2 = 'b' ((1,2),(2,1))
    // rotation r sample maps (orig frame):
    //   r0: (+dr,+dc)  r1: (+dc,-dr)  r2: (-dr,-dc)  r3: (-dc,+dr)
    int bi[12], ci[12];
    // h
    bi[0]  = r_0[xp1];   ci[0]  = r_0[xp2];
    bi[1]  = r_p1[x];    ci[1]  = r_p2[x];
    bi[2]  = r_0[xm1];   ci[2]  = r_0[xm2];
    bi[3]  = r_m1[x];    ci[3]  = r_m2[x];
    // d
    bi[4]  = r_p1[xp1];  ci[4]  = r_p2[xp2];
    bi[5]  = r_p1[xm1];  ci[5]  = r_p2[xm2];
    bi[6]  = r_m1[xm1];  ci[6]  = r_m2[xm2];
    bi[7]  = r_m1[xp1];  ci[7]  = r_m2[xp2];
    // b
    bi[8]  = r_p1[xp2];  ci[8]  = r_p2[xp1];
    bi[9]  = r_p2[xm1];  ci[9]  = r_p1[xm2];
    bi[10] = r_m1[xm2];  ci[10] = r_m2[xm1];
    bi[11] = r_m2[xp1];  ci[11] = r_m1[xp2];

    const long base = (long)a << 16;  // a * 65536

    // Issue all 12 gathers back-to-back for max MLP.
    float4 w[12];
#pragma unroll
    for (int k = 0; k < 12; ++k) {
        const long idx = base + ((long)bi[k] << 8) + (long)ci[k];
        const float4* tbl = (k < 4) ? wh : (k < 8) ? wd : wb;
        w[k] = __ldg(&tbl[idx]);
    }

    // Accumulate with per-rotation 2x2 permutation:
    // r0: identity; r1: acc(p,q)+=w[2(1-q)+p]; r2: w[3-2p-q]; r3: w[2q+(1-p)]
    float a0 = 0.f, a1 = 0.f, a2 = 0.f, a3 = 0.f;
#pragma unroll
    for (int k = 0; k < 12; ++k) {
        const float4 v = w[k];
        switch (k & 3) {
            case 0: a0 += v.x; a1 += v.y; a2 += v.z; a3 += v.w; break;
            case 1: a0 += v.z; a1 += v.x; a2 += v.w; a3 += v.y; break;
            case 2: a0 += v.w; a1 += v.z; a2 += v.y; a3 += v.x; break;
            case 3: a0 += v.y; a1 += v.w; a2 += v.x; a3 += v.z; break;
        }
    }

    const float s = 1.0f / 3.0f;
    float* o = out + (size_t)bz * (2 * NN) * (2 * NN)
                   + (size_t)(2 * y) * (2 * NN) + (size_t)(2 * x);
    *reinterpret_cast<float2*>(o)          = make_float2(a0 * s, a1 * s);
    *reinterpret_cast<float2*>(o + 2 * NN) = make_float2(a2 * s, a3 * s);
}

extern "C" void kernel_launch(void* const* d_in, const int* in_sizes, int n_in,
                              void* d_out, int out_size)
{
    const int*    img = (const int*)d_in[0];
    const float4* wh  = (const float4*)d_in[1];
    const float4* wd  = (const float4*)d_in[2];
    const float4* wb  = (const float4*)d_in[3];
    float*        out = (float*)d_out;

    dim3 block(BDIM, 1, 1);
    dim3 grid(NN / BDIM, NN, 8);
    hdblut_kernel<<<grid, block>>>(img, wh, wd, wb, out);
}